// round 16
// baseline (speedup 1.0000x reference)
#include <cuda_runtime.h>
#include <cstdint>

#define NA   16
#define NR   32
#define TPB  128     // 4 warps; warp w handles rules 8w..8w+7
#define RPW  8       // rules per warp
#define SPT  2       // samples per thread
#define SPB  64      // samples per block (32 lanes * SPT, shared by all 4 warps)

static __device__ __forceinline__ unsigned long long pack2(float lo, float hi) {
    unsigned long long r;
    asm("mov.b64 %0, {%1, %2};" : "=l"(r) : "f"(lo), "f"(hi));
    return r;
}
static __device__ __forceinline__ void unpack2(unsigned long long v, float& lo, float& hi) {
    asm("mov.b64 {%0, %1}, %2;" : "=f"(lo), "=f"(hi) : "l"(v));
}
static __device__ __forceinline__ unsigned long long fma2(
    unsigned long long a, unsigned long long b, unsigned long long c) {
    unsigned long long d;
    asm("fma.rn.f32x2 %0, %1, %2, %3;" : "=l"(d) : "l"(a), "l"(b), "l"(c));
    return d;
}
static __device__ __forceinline__ float ex2(float x) {
    float y;
    asm("ex2.approx.f32 %0, %1;" : "=f"(y) : "f"(x));
    return y;
}

__global__ void __launch_bounds__(TPB, 6)
tsk_kernel(const float* __restrict__ input,
           const float* __restrict__ frbw,
           const float* __restrict__ C,
           float* __restrict__ out, int B)
{
    // Coefficient table, k-packed u64 pairs (~6.7 KB), built once per block.
    // Per rule r: [0..7]=P pairs, [8..15]=Q pairs, [16..23]=C pairs,
    //             [24]=(rc_even, rc_odd), [25]=(C0, 0).
    __shared__ unsigned long long sco[NR][26];
    // Rule-group partials: red[group][spt][lane] = (num, den)  (2 KB)
    __shared__ float2 red[4][SPT][32];

    const float L2E = 1.4426950408889634f;
    const int tid  = threadIdx.x;
    const int w    = tid >> 5;
    const int lane = tid & 31;

    // ---- build coefficient table (2 kpair slots/thread) ----
    // Faithful to reference: idx = r*A + k; (sigma, center) = FRB_W[idx], FRB_W[idx+1]
    for (int i = tid; i < NR * 8; i += TPB) {
        int r = i >> 3, j = i & 7;
        int k0 = 2 * j;
        float sig0 = frbw[r * NA + k0];
        float cen0 = frbw[r * NA + k0 + 1];
        float is0 = 1.0f / (sig0 * sig0);
        float p0 = -0.5f * is0 * L2E;
        float q0 = is0 * cen0 * L2E;
        float sig1 = frbw[r * NA + k0 + 1];
        float cen1 = frbw[r * NA + k0 + 2];
        float is1 = 1.0f / (sig1 * sig1);
        float p1 = -0.5f * is1 * L2E;
        float q1 = is1 * cen1 * L2E;
        sco[r][j]      = pack2(p0, p1);
        sco[r][8 + j]  = pack2(q0, q1);
        sco[r][16 + j] = pack2(C[r * (NA + 1) + k0 + 1], C[r * (NA + 1) + k0 + 2]);
    }
    if (tid < NR) {
        int r = tid;
        float rce = 0.0f, rco = 0.0f;
        #pragma unroll
        for (int j = 0; j < 8; j++) {
            float sig0 = frbw[r * NA + 2 * j];
            float cen0 = frbw[r * NA + 2 * j + 1];
            rce += -0.5f / (sig0 * sig0) * L2E * cen0 * cen0;
            float sig1 = frbw[r * NA + 2 * j + 1];
            float cen1 = frbw[r * NA + 2 * j + 2];
            rco += -0.5f / (sig1 * sig1) * L2E * cen1 * cen1;
        }
        sco[r][24] = pack2(rce, rco);
        sco[r][25] = pack2(C[r * (NA + 1)], 0.0f);
    }
    __syncthreads();

    // ---- thread-private X: SPT rows, k-packed (same 64 samples in all warps) ----
    const int base = blockIdx.x * SPB;
    unsigned long long X[SPT][8];
    #pragma unroll
    for (int i = 0; i < SPT; i++) {
        int rr = base + lane + 32 * i;
        int cl = (rr < B) ? rr : (B - 1);
        const float4* g = (const float4*)(input + (size_t)cl * NA);
        float4 v0 = g[0], v1 = g[1], v2 = g[2], v3 = g[3];
        X[i][0] = pack2(v0.x, v0.y);  X[i][1] = pack2(v0.z, v0.w);
        X[i][2] = pack2(v1.x, v1.y);  X[i][3] = pack2(v1.z, v1.w);
        X[i][4] = pack2(v2.x, v2.y);  X[i][5] = pack2(v2.z, v2.w);
        X[i][6] = pack2(v3.x, v3.y);  X[i][7] = pack2(v3.z, v3.w);
    }

    float num0 = 0.f, num1 = 0.f, den0 = 0.f, den1 = 0.f;

    // ---- sweep this warp's 8 rules; coefficients warp-uniform broadcast ----
    const int r0 = w * RPW;
    #pragma unroll 1      // body ~100 instrs: L0-resident
    for (int r = r0; r < r0 + RPW; r++) {
        const unsigned long long* cw = sco[r];
        unsigned long long RC = cw[24];
        unsigned long long C0 = cw[25];
        unsigned long long e0 = RC, e1 = RC;
        unsigned long long h0 = C0, h1 = C0;
        #pragma unroll
        for (int k = 0; k < 8; k++) {
            unsigned long long Pk = cw[k];
            unsigned long long Qk = cw[8 + k];
            unsigned long long Ck = cw[16 + k];
            unsigned long long t0 = fma2(Pk, X[0][k], Qk);
            unsigned long long t1 = fma2(Pk, X[1][k], Qk);
            e0 = fma2(t0, X[0][k], e0);
            e1 = fma2(t1, X[1][k], e1);
            h0 = fma2(Ck, X[0][k], h0);
            h1 = fma2(Ck, X[1][k], h1);
        }
        float ae, ao, be, bo, he0, ho0, he1, ho1;
        unpack2(e0, ae, ao);
        unpack2(e1, be, bo);
        unpack2(h0, he0, ho0);
        unpack2(h1, he1, ho1);
        float u0 = ex2(ae + ao);
        float u1 = ex2(be + bo);
        num0 = fmaf(u0, he0 + ho0, num0);  den0 += u0;
        num1 = fmaf(u1, he1 + ho1, num1);  den1 += u1;
    }

    // ---- combine rule-group partials across the 4 warps ----
    red[w][0][lane] = make_float2(num0, den0);
    red[w][1][lane] = make_float2(num1, den1);
    __syncthreads();

    // warps 0 and 1 emit the block's 64 outputs (coalesced per warp)
    if (w < SPT) {
        float2 p0 = red[0][w][lane];
        float2 p1 = red[1][w][lane];
        float2 p2 = red[2][w][lane];
        float2 p3 = red[3][w][lane];
        float n = (p0.x + p1.x) + (p2.x + p3.x);
        float d = (p0.y + p1.y) + (p2.y + p3.y);
        int s = base + lane + 32 * w;
        if (s < B) out[s] = __fdividef(n, d);
    }
}

extern "C" void kernel_launch(void* const* d_in, const int* in_sizes, int n_in,
                              void* d_out, int out_size)
{
    const float* input = (const float*)d_in[0];   // [B, 16] fp32
    const float* frbw  = (const float*)d_in[1];   // [1024]  fp32
    const float* Cm    = (const float*)d_in[2];   // [32,17] fp32
    float* out = (float*)d_out;                   // [B]     fp32

    int B = in_sizes[0] / NA;
    int blocks = (B + SPB - 1) / SPB;             // 1024 for B=65536 (exact)
    tsk_kernel<<<blocks, TPB>>>(input, frbw, Cm, out, B);
}

// round 17
// speedup vs baseline: 1.0021x; 1.0021x over previous
#include <cuda_runtime.h>
#include <cstdint>

#define NA   16
#define NR   32
#define TPB  128     // 4 warps; warp w handles rules 8w..8w+7
#define RPW  8       // rules per warp
#define SPT  4       // samples per thread
#define SPB  128     // samples per block (32 lanes * SPT, shared by all 4 warps)

static __device__ __forceinline__ unsigned long long pack2(float lo, float hi) {
    unsigned long long r;
    asm("mov.b64 %0, {%1, %2};" : "=l"(r) : "f"(lo), "f"(hi));
    return r;
}
static __device__ __forceinline__ void unpack2(unsigned long long v, float& lo, float& hi) {
    asm("mov.b64 {%0, %1}, %2;" : "=f"(lo), "=f"(hi) : "l"(v));
}
static __device__ __forceinline__ unsigned long long fma2(
    unsigned long long a, unsigned long long b, unsigned long long c) {
    unsigned long long d;
    asm("fma.rn.f32x2 %0, %1, %2, %3;" : "=l"(d) : "l"(a), "l"(b), "l"(c));
    return d;
}
static __device__ __forceinline__ float ex2(float x) {
    float y;
    asm("ex2.approx.f32 %0, %1;" : "=f"(y) : "f"(x));
    return y;
}

__global__ void __launch_bounds__(TPB, 3)
tsk_kernel(const float* __restrict__ input,
           const float* __restrict__ frbw,
           const float* __restrict__ C,
           float* __restrict__ out, int B)
{
    // Coefficient table, k-packed u64 pairs, 26 u64 per rule (row = 208B, 16B-aligned).
    // Per rule r: [0..7]=P pairs, [8..15]=Q pairs, [16..23]=C pairs,
    //             [24]=(rc_even, rc_odd), [25]=(C0, 0).
    __shared__ unsigned long long sco[NR][26];
    // Rule-group partials: red[group][spt][lane] = (num, den)
    __shared__ float2 red[4][SPT][32];

    const float L2E = 1.4426950408889634f;
    const int tid  = threadIdx.x;
    const int w    = tid >> 5;
    const int lane = tid & 31;

    // ---- build coefficient table (2 kpair slots/thread) ----
    // Faithful to reference: idx = r*A + k; (sigma, center) = FRB_W[idx], FRB_W[idx+1]
    for (int i = tid; i < NR * 8; i += TPB) {
        int r = i >> 3, j = i & 7;
        int k0 = 2 * j;
        float sig0 = frbw[r * NA + k0];
        float cen0 = frbw[r * NA + k0 + 1];
        float is0 = 1.0f / (sig0 * sig0);
        float p0 = -0.5f * is0 * L2E;
        float q0 = is0 * cen0 * L2E;
        float sig1 = frbw[r * NA + k0 + 1];
        float cen1 = frbw[r * NA + k0 + 2];
        float is1 = 1.0f / (sig1 * sig1);
        float p1 = -0.5f * is1 * L2E;
        float q1 = is1 * cen1 * L2E;
        sco[r][j]      = pack2(p0, p1);
        sco[r][8 + j]  = pack2(q0, q1);
        sco[r][16 + j] = pack2(C[r * (NA + 1) + k0 + 1], C[r * (NA + 1) + k0 + 2]);
    }
    if (tid < NR) {
        int r = tid;
        float rce = 0.0f, rco = 0.0f;
        #pragma unroll
        for (int j = 0; j < 8; j++) {
            float sig0 = frbw[r * NA + 2 * j];
            float cen0 = frbw[r * NA + 2 * j + 1];
            rce += -0.5f / (sig0 * sig0) * L2E * cen0 * cen0;
            float sig1 = frbw[r * NA + 2 * j + 1];
            float cen1 = frbw[r * NA + 2 * j + 2];
            rco += -0.5f / (sig1 * sig1) * L2E * cen1 * cen1;
        }
        sco[r][24] = pack2(rce, rco);
        sco[r][25] = pack2(C[r * (NA + 1)], 0.0f);
    }
    __syncthreads();

    // ---- thread-private X: SPT rows (same 128 samples in all 4 warps) ----
    const int base = blockIdx.x * SPB;
    unsigned long long X[SPT][8];
    #pragma unroll
    for (int i = 0; i < SPT; i++) {
        int rr = base + lane + 32 * i;
        int cl = (rr < B) ? rr : (B - 1);
        const float4* g = (const float4*)(input + (size_t)cl * NA);
        float4 v0 = g[0], v1 = g[1], v2 = g[2], v3 = g[3];
        X[i][0] = pack2(v0.x, v0.y);  X[i][1] = pack2(v0.z, v0.w);
        X[i][2] = pack2(v1.x, v1.y);  X[i][3] = pack2(v1.z, v1.w);
        X[i][4] = pack2(v2.x, v2.y);  X[i][5] = pack2(v2.z, v2.w);
        X[i][6] = pack2(v3.x, v3.y);  X[i][7] = pack2(v3.z, v3.w);
    }

    float num[SPT] = {0.f, 0.f, 0.f, 0.f};
    float den[SPT] = {0.f, 0.f, 0.f, 0.f};

    const int r0 = w * RPW;

    // ---- prologue: load rule r0's coefficients into registers ----
    ulonglong2 Pb[4], Qb[4], Cb[4], RCb;
    {
        const ulonglong2* c2 = (const ulonglong2*)sco[r0];
        Pb[0] = c2[0];  Pb[1] = c2[1];  Pb[2] = c2[2];  Pb[3] = c2[3];
        Qb[0] = c2[4];  Qb[1] = c2[5];  Qb[2] = c2[6];  Qb[3] = c2[7];
        Cb[0] = c2[8];  Cb[1] = c2[9];  Cb[2] = c2[10]; Cb[3] = c2[11];
        RCb   = c2[12];
    }

    // ---- sweep 8 rules with in-place rotating prefetch of rule r+1 ----
    #pragma unroll 1
    for (int ri = 0; ri < RPW; ri++) {
        // prefetch source: next rule (wraps to r0 on last iter; harmless)
        const ulonglong2* nx = (const ulonglong2*)sco[r0 + ((ri + 1) & 7)];

        unsigned long long RC = RCb.x;   // (rc_even, rc_odd)
        unsigned long long C0 = RCb.y;   // (c0, 0)
        RCb = nx[12];                    // reload immediately (used only at init)

        unsigned long long e0 = RC, e1 = RC, e2 = RC, e3 = RC;
        unsigned long long h0 = C0, h1 = C0, h2 = C0, h3 = C0;

        #pragma unroll
        for (int m = 0; m < 4; m++) {    // two k-pairs per m: k = 4m..4m+3
            ulonglong2 Pc = Pb[m], Qc = Qb[m], Cc = Cb[m];
            // reload chunk m from next rule right after copying to locals
            Pb[m] = nx[m];
            Qb[m] = nx[4 + m];
            Cb[m] = nx[8 + m];

            // k-pair 2m (covers k=4m,4m+1)
            {
                unsigned long long t0 = fma2(Pc.x, X[0][2 * m], Qc.x);
                unsigned long long t1 = fma2(Pc.x, X[1][2 * m], Qc.x);
                unsigned long long t2 = fma2(Pc.x, X[2][2 * m], Qc.x);
                unsigned long long t3 = fma2(Pc.x, X[3][2 * m], Qc.x);
                e0 = fma2(t0, X[0][2 * m], e0);
                e1 = fma2(t1, X[1][2 * m], e1);
                e2 = fma2(t2, X[2][2 * m], e2);
                e3 = fma2(t3, X[3][2 * m], e3);
                h0 = fma2(Cc.x, X[0][2 * m], h0);
                h1 = fma2(Cc.x, X[1][2 * m], h1);
                h2 = fma2(Cc.x, X[2][2 * m], h2);
                h3 = fma2(Cc.x, X[3][2 * m], h3);
            }
            // k-pair 2m+1 (covers k=4m+2,4m+3)
            {
                unsigned long long t0 = fma2(Pc.y, X[0][2 * m + 1], Qc.y);
                unsigned long long t1 = fma2(Pc.y, X[1][2 * m + 1], Qc.y);
                unsigned long long t2 = fma2(Pc.y, X[2][2 * m + 1], Qc.y);
                unsigned long long t3 = fma2(Pc.y, X[3][2 * m + 1], Qc.y);
                e0 = fma2(t0, X[0][2 * m + 1], e0);
                e1 = fma2(t1, X[1][2 * m + 1], e1);
                e2 = fma2(t2, X[2][2 * m + 1], e2);
                e3 = fma2(t3, X[3][2 * m + 1], e3);
                h0 = fma2(Cc.y, X[0][2 * m + 1], h0);
                h1 = fma2(Cc.y, X[1][2 * m + 1], h1);
                h2 = fma2(Cc.y, X[2][2 * m + 1], h2);
                h3 = fma2(Cc.y, X[3][2 * m + 1], h3);
            }
        }

        float ae, ao, be, bo, ce, co, de, df;
        float he0, ho0, he1, ho1, he2, ho2, he3, ho3;
        unpack2(e0, ae, ao);  unpack2(e1, be, bo);
        unpack2(e2, ce, co);  unpack2(e3, de, df);
        unpack2(h0, he0, ho0);  unpack2(h1, he1, ho1);
        unpack2(h2, he2, ho2);  unpack2(h3, he3, ho3);
        float u0 = ex2(ae + ao);
        float u1 = ex2(be + bo);
        float u2 = ex2(ce + co);
        float u3 = ex2(de + df);
        num[0] = fmaf(u0, he0 + ho0, num[0]);  den[0] += u0;
        num[1] = fmaf(u1, he1 + ho1, num[1]);  den[1] += u1;
        num[2] = fmaf(u2, he2 + ho2, num[2]);  den[2] += u2;
        num[3] = fmaf(u3, he3 + ho3, num[3]);  den[3] += u3;
    }

    // ---- combine rule-group partials across the 4 warps ----
    #pragma unroll
    for (int i = 0; i < SPT; i++) red[w][i][lane] = make_float2(num[i], den[i]);
    __syncthreads();

    // thread (w, lane) outputs sample slot i = w for lane `lane`
    {
        float2 p0 = red[0][w][lane];
        float2 p1 = red[1][w][lane];
        float2 p2 = red[2][w][lane];
        float2 p3 = red[3][w][lane];
        float n = (p0.x + p1.x) + (p2.x + p3.x);
        float d = (p0.y + p1.y) + (p2.y + p3.y);
        int s = base + lane + 32 * w;   // coalesced per warp
        if (s < B) out[s] = __fdividef(n, d);
    }
}

extern "C" void kernel_launch(void* const* d_in, const int* in_sizes, int n_in,
                              void* d_out, int out_size)
{
    const float* input = (const float*)d_in[0];   // [B, 16] fp32
    const float* frbw  = (const float*)d_in[1];   // [1024]  fp32
    const float* Cm    = (const float*)d_in[2];   // [32,17] fp32
    float* out = (float*)d_out;                   // [B]     fp32

    int B = in_sizes[0] / NA;
    int blocks = (B + SPB - 1) / SPB;             // 512 for B=65536 (exact)
    tsk_kernel<<<blocks, TPB>>>(input, frbw, Cm, out, B);
}